// round 5
// baseline (speedup 1.0000x reference)
#include <cuda_runtime.h>
#include <math.h>

#define BATCH 1024
#define SEQ   200
#define EMB   128
#define TSTEPS 199
#define PW    640      // P columns: [K(128) | V(128) | KP(128) | Q2(128) | Q3(128)]
#define AST   204      // attn smem row stride (per head)
#define NEGF  (-3.402823466e38f)

// ---------------- device scratch ----------------
__device__ float g_P[(size_t)BATCH * SEQ * PW];
__device__ float g_Wcat[EMB * PW];
__device__ float g_qhat[BATCH * EMB];
__device__ float g_qvec[2 * EMB];

// ---------------- build combined weights: [Wk | Wv | Wp@Wo^T | Wq2 | Wq3] -------
__global__ void wcat_kernel(const float* __restrict__ Wk, const float* __restrict__ Wv,
                            const float* __restrict__ Wo, const float* __restrict__ Wp,
                            const float* __restrict__ Wq) {
    int e = threadIdx.x;
    int c = blockIdx.x;
    float v;
    if (c < 128) {
        v = Wk[e * 128 + c];
    } else if (c < 256) {
        v = Wv[e * 128 + (c - 128)];
    } else if (c < 384) {
        int i = c - 256;
        float s = 0.f;
        for (int j = 0; j < 128; j++) s += Wp[e * 128 + j] * Wo[i * 128 + j];
        v = s;
    } else if (c < 512) {
        v = Wq[(128 + e) * 128 + (c - 384)];
    } else {
        v = Wq[(256 + e) * 128 + (c - 512)];
    }
    g_Wcat[e * PW + c] = v;
}

// ---------------- h_hat mean + qhat = h_hat @ Wq1 (+ vl/vf projections) ---------
__global__ void prep_kernel(const float* __restrict__ enc, const float* __restrict__ vl,
                            const float* __restrict__ vf, const float* __restrict__ Wq) {
    __shared__ float hh[EMB];
    int b = blockIdx.x, e = threadIdx.x;
    const float* p = enc + (size_t)b * SEQ * EMB + e;
    float s = 0.f;
    for (int i = 0; i < SEQ; i++) s += p[(size_t)i * EMB];
    hh[e] = s * (1.0f / (float)SEQ);
    __syncthreads();
    float q = 0.f;
    for (int k = 0; k < 128; k++) q += hh[k] * Wq[k * 128 + e];
    g_qhat[b * EMB + e] = q;
    if (b == 0) {
        float a = 0.f, c = 0.f;
        for (int k = 0; k < 128; k++) {
            a += vl[k] * Wq[(128 + k) * 128 + e];
            c += vf[k] * Wq[(256 + k) * 128 + e];
        }
        g_qvec[e] = a;
        g_qvec[128 + e] = c;
    }
}

// ---------------- SGEMM: g_P[204800,640] = enc[204800,128] @ g_Wcat[128,640] ----
__global__ __launch_bounds__(512, 1) void gemm_kernel(const float* __restrict__ A) {
    extern __shared__ float smg[];
    float* As = smg;               // As[k*132 + m]
    float* Bs = smg + 128 * 132;   // Bs[k*128 + n]
    int m0 = blockIdx.x * 128, n0 = blockIdx.y * 128;
    int tid = threadIdx.x;
#pragma unroll
    for (int it = 0; it < 32; it++) {
        int idx = tid + it * 512;
        int k = idx & 127, m = idx >> 7;
        As[k * 132 + m] = A[(size_t)(m0 + m) * 128 + k];
        Bs[m * 128 + k] = g_Wcat[m * PW + n0 + k];
    }
    __syncthreads();
    int tx = tid & 31, ty = tid >> 5;
    float acc[8][4];
#pragma unroll
    for (int i = 0; i < 8; i++)
#pragma unroll
        for (int j = 0; j < 4; j++) acc[i][j] = 0.f;
#pragma unroll 4
    for (int k = 0; k < 128; k++) {
        float4 a0 = *(float4*)&As[k * 132 + ty * 8];
        float4 a1 = *(float4*)&As[k * 132 + ty * 8 + 4];
        float4 b  = *(float4*)&Bs[k * 128 + tx * 4];
        float av[8] = {a0.x, a0.y, a0.z, a0.w, a1.x, a1.y, a1.z, a1.w};
#pragma unroll
        for (int i = 0; i < 8; i++) {
            acc[i][0] += av[i] * b.x;
            acc[i][1] += av[i] * b.y;
            acc[i][2] += av[i] * b.z;
            acc[i][3] += av[i] * b.w;
        }
    }
#pragma unroll
    for (int i = 0; i < 8; i++) {
        float* cr = &g_P[(size_t)(m0 + ty * 8 + i) * PW + n0 + tx * 4];
        *(float4*)cr = make_float4(acc[i][0], acc[i][1], acc[i][2], acc[i][3]);
    }
}

// -------- persistent per-batch greedy decode: K, V, KP all in registers --------
__global__ __launch_bounds__(512) void decode_kernel(float* __restrict__ outLogits,
                                                     float* __restrict__ outLogp,
                                                     float* __restrict__ outSol) {
    __shared__ float attn[8 * AST];     // unnormalized attn per head
    __shared__ float ctxp[16 * 128];    // per-warp ctx partials
    __shared__ float qv[EMB];
    __shared__ float ctx[EMB];
    __shared__ float wmax[16], wsum[16], redv[16], reds[16];
    __shared__ int   redi[16];
    __shared__ unsigned maskw[8];
    __shared__ int   sols[SEQ];
    __shared__ float s_logp, s_bmax;
    __shared__ int   s_bi;

    int tid = threadIdx.x, lane = tid & 31, w = tid >> 5;
    int b = blockIdx.x;
    const float* __restrict__ Pb = g_P + (size_t)b * SEQ * PW;

    // ---- K in registers: warp w = (head h, sub), rows r=0..3: s = sub*128+32r+lane
    int h = w >> 1, sub = w & 1;
    float4 kreg[4][4];
#pragma unroll
    for (int r = 0; r < 4; r++) {
        int s = sub * 128 + (r << 5) + lane;
        if (s < SEQ) {
            const float4* kp = (const float4*)&Pb[(size_t)s * PW + (h << 4)];
            kreg[r][0] = kp[0]; kreg[r][1] = kp[1]; kreg[r][2] = kp[2]; kreg[r][3] = kp[3];
        } else {
            kreg[r][0] = kreg[r][1] = kreg[r][2] = kreg[r][3] = make_float4(0.f, 0.f, 0.f, 0.f);
        }
    }

    // ---- V in registers: warp w owns s in [vs0, vs0+vcnt), lane owns e = 4*lane..+3
    int vs0, vcnt;
    if (w < 8) { vs0 = w * 13; vcnt = 13; } else { vs0 = 104 + (w - 8) * 12; vcnt = 12; }
    float4 vreg[13];
#pragma unroll
    for (int i = 0; i < 13; i++) {
        if (i < vcnt)
            vreg[i] = *(const float4*)&Pb[(size_t)(vs0 + i) * PW + 128 + (lane << 2)];
        else
            vreg[i] = make_float4(0.f, 0.f, 0.f, 0.f);
    }

    // ---- KP in registers: threads t<400, s = t>>1, half = t&1, 64 e's per thread
    int ps = tid >> 1, phalf = tid & 1;
    bool pvalid = (tid < 2 * SEQ);
    float4 kpreg[16];
#pragma unroll
    for (int j = 0; j < 16; j++) {
        if (pvalid)
            kpreg[j] = *(const float4*)&Pb[(size_t)ps * PW + 256 + (phalf << 6) + (j << 2)];
        else
            kpreg[j] = make_float4(0.f, 0.f, 0.f, 0.f);
    }

    float qhat_r = 0.f, q2r = 0.f, q3r = 0.f;
    if (tid < 128) {
        qhat_r = g_qhat[b * EMB + tid];
        q2r = g_qvec[tid];          // t=0: last = vl
        q3r = g_qvec[128 + tid];    // t=0: first = vf
    }
    if (tid < 8) maskw[tid] = (tid == 0) ? 1u : 0u;
    if (tid == 0) { s_logp = 0.f; sols[0] = 0; }
    __syncthreads();

    const float inv_scale = 0.08838834764831845f;   // 1/sqrt(128)

    for (int t = 0; t < TSTEPS; t++) {
        // ---- [1] accumulate previous CE + build q (pre-scaled by 1/sqrt(dh)) ----
        if (tid == 0 && t > 0) {
            float tot = 0.f;
#pragma unroll
            for (int i = 0; i < 13; i++) tot += reds[i];
            s_logp += logf(tot);
        }
        if (tid < 128) qv[tid] = (qhat_r + q2r + q3r) * 0.25f;
        __syncthreads();

        // ---- [2a] scores from register K, per-warp max ----
        float sc[4];
        {
            const float4* qp = (const float4*)&qv[h << 4];
            float4 q0 = qp[0], q1 = qp[1], q2 = qp[2], q3 = qp[3];
#pragma unroll
            for (int r = 0; r < 4; r++) {
                int s = sub * 128 + (r << 5) + lane;
                float v;
                v  = q0.x * kreg[r][0].x + q0.y * kreg[r][0].y + q0.z * kreg[r][0].z + q0.w * kreg[r][0].w;
                v += q1.x * kreg[r][1].x + q1.y * kreg[r][1].y + q1.z * kreg[r][1].z + q1.w * kreg[r][1].w;
                v += q2.x * kreg[r][2].x + q2.y * kreg[r][2].y + q2.z * kreg[r][2].z + q2.w * kreg[r][2].w;
                v += q3.x * kreg[r][3].x + q3.y * kreg[r][3].y + q3.z * kreg[r][3].z + q3.w * kreg[r][3].w;
                bool ok = (s < SEQ) && !((maskw[4 * sub + r] >> lane) & 1u);
                sc[r] = ok ? v : NEGF;
            }
            float mx = fmaxf(fmaxf(sc[0], sc[1]), fmaxf(sc[2], sc[3]));
#pragma unroll
            for (int o = 16; o; o >>= 1) mx = fmaxf(mx, __shfl_xor_sync(0xffffffffu, mx, o));
            if (lane == 0) wmax[w] = mx;
        }
        __syncthreads();

        // ---- [2b] exp (head max), store unnormalized attn, per-warp sum ----
        {
            float mx = fmaxf(wmax[2 * h], wmax[2 * h + 1]);
            float ssum = 0.f;
#pragma unroll
            for (int r = 0; r < 4; r++) {
                int s = sub * 128 + (r << 5) + lane;
                float er = expf(sc[r] - mx);      // NEGF -> 0
                ssum += er;
                if (s < SEQ) attn[h * AST + s] = er;
            }
#pragma unroll
            for (int o = 16; o; o >>= 1) ssum += __shfl_xor_sync(0xffffffffu, ssum, o);
            if (lane == 0) wsum[w] = ssum;
        }
        __syncthreads();

        // ---- [3] ctx partials from register V (attn broadcast from smem) ----
        {
            int hh = lane >> 2;
            const float* arow = &attn[hh * AST];
            float a0 = 0.f, a1 = 0.f, a2 = 0.f, a3 = 0.f;
#pragma unroll
            for (int i = 0; i < 13; i++) {
                if (i < vcnt) {
                    float a = arow[vs0 + i];
                    a0 += a * vreg[i].x; a1 += a * vreg[i].y;
                    a2 += a * vreg[i].z; a3 += a * vreg[i].w;
                }
            }
            *(float4*)&ctxp[w * 128 + (lane << 2)] = make_float4(a0, a1, a2, a3);
        }
        __syncthreads();

        // ---- [4] ctx combine + softmax normalization ----
        if (tid < 128) {
            float s = 0.f;
#pragma unroll
            for (int i = 0; i < 16; i++) s += ctxp[i * 128 + tid];
            int hd = tid >> 4;
            float inv = 1.f / (wsum[2 * hd] + wsum[2 * hd + 1]);
            ctx[tid] = s * inv;
        }
        __syncthreads();

        // ---- [5] pointer logits from register KP (ctx broadcast), pair-combine ----
        float myval = NEGF;
        if (w < 13) {
            float z0 = 0.f, z1 = 0.f, z2 = 0.f, z3 = 0.f;
#pragma unroll
            for (int j = 0; j < 16; j++) {
                float4 c4 = *(const float4*)&ctx[(phalf << 6) + (j << 2)];
                z0 += c4.x * kpreg[j].x;
                z1 += c4.y * kpreg[j].y;
                z2 += c4.z * kpreg[j].z;
                z3 += c4.w * kpreg[j].w;
            }
            float z = (z0 + z1) + (z2 + z3);
            z += __shfl_xor_sync(0xffffffffu, z, 1);
            if (pvalid && phalf == 0) {
                float u = 10.f * tanhf(z * inv_scale);
                outLogits[((size_t)b * TSTEPS + t) * SEQ + ps] = u;
                if (!((maskw[ps >> 5] >> (ps & 31)) & 1u)) myval = u;
            }
            float val = myval; int vidx = pvalid ? ps : 0x7fffffff;
#pragma unroll
            for (int o = 16; o; o >>= 1) {
                float ov = __shfl_xor_sync(0xffffffffu, val, o);
                int   oi = __shfl_xor_sync(0xffffffffu, vidx, o);
                if (ov > val || (ov == val && oi < vidx)) { val = ov; vidx = oi; }
            }
            if (lane == 0) { redv[w] = val; redi[w] = vidx; }
        }
        __syncthreads();

        // ---- [6] argmax finalize + mask/sol update ----
        if (tid == 0) {
            float bm = redv[0]; int bi = redi[0];
#pragma unroll
            for (int i = 1; i < 13; i++)
                if (redv[i] > bm) { bm = redv[i]; bi = redi[i]; }
            s_bmax = bm; s_bi = bi;
            maskw[bi >> 5] |= (1u << (bi & 31));
            sols[t + 1] = bi;
        }
        __syncthreads();

        // ---- [7] CE exp-sums + prefetch next-step q rows ----
        if (w < 13) {
            float e = expf(myval - s_bmax);   // masked / invalid lanes -> 0
#pragma unroll
            for (int o = 16; o; o >>= 1) e += __shfl_xor_sync(0xffffffffu, e, o);
            if (lane == 0) reds[w] = e;
        }
        if (tid < 128) {
            int bi = s_bi;
            q2r = Pb[(size_t)bi * PW + 384 + tid];             // Q2[b, idx]
            if (t == 0) q3r = Pb[(size_t)bi * PW + 512 + tid]; // Q3[b, idx0]
        }
        __syncthreads();
    }

    if (tid == 0 && outLogp) {
        float tot = 0.f;
        for (int i = 0; i < 13; i++) tot += reds[i];
        outLogp[b] = s_logp + logf(tot);
    }
    if (outSol && tid < SEQ) outSol[b * SEQ + tid] = (float)sols[tid];
}

// -------------------------------- launcher --------------------------------------
extern "C" void kernel_launch(void* const* d_in, const int* in_sizes, int n_in,
                              void* d_out, int out_size) {
    const float* enc = (const float*)d_in[0];
    const float* vl = (const float*)d_in[3];
    const float* vf = (const float*)d_in[4];
    const float* Wq = (const float*)d_in[5];
    const float* Wk = (const float*)d_in[6];
    const float* Wv = (const float*)d_in[7];
    const float* Wo = (const float*)d_in[8];
    const float* Wp = (const float*)d_in[9];

    float* out = (float*)d_out;
    size_t L = (size_t)BATCH * TSTEPS * SEQ;
    float* outLogp = nullptr;
    float* outSol  = nullptr;
    if ((size_t)out_size >= L + BATCH) outLogp = out + L;
    if ((size_t)out_size >= L + BATCH + (size_t)BATCH * SEQ) outSol = out + L + BATCH;

    const int gemm_smem = (128 * 132 + 128 * 128) * 4;   // 133,120 B
    cudaFuncSetAttribute(gemm_kernel, cudaFuncAttributeMaxDynamicSharedMemorySize, gemm_smem);

    wcat_kernel<<<PW, 128>>>(Wk, Wv, Wo, Wp, Wq);
    prep_kernel<<<BATCH, 128>>>(enc, vl, vf, Wq);
    gemm_kernel<<<dim3(BATCH * SEQ / 128, PW / 128), 512, gemm_smem>>>(enc);
    decode_kernel<<<BATCH, 512>>>(out, outLogp, outSol);
}

// round 6
// speedup vs baseline: 2.1320x; 2.1320x over previous
#include <cuda_runtime.h>
#include <math.h>

#define BATCH 1024
#define SEQ   200
#define EMB   128
#define TSTEPS 199
#define PW    640      // P columns: [K(128) | V(128) | KP(128) | Q2(128) | Q3(128)]
#define AST   204      // attn smem row stride (per head)
#define KPSTRIDE 132   // KP smem row stride (per s) -> bank-shift 4 per s
#define NEGF  (-3.402823466e38f)

// ---------------- device scratch ----------------
__device__ float g_P[(size_t)BATCH * SEQ * PW];
__device__ float g_Wcat[EMB * PW];
__device__ float g_qhat[BATCH * EMB];
__device__ float g_qvec[2 * EMB];

// ---------------- build combined weights: [Wk | Wv | Wp@Wo^T | Wq2 | Wq3] -------
__global__ void wcat_kernel(const float* __restrict__ Wk, const float* __restrict__ Wv,
                            const float* __restrict__ Wo, const float* __restrict__ Wp,
                            const float* __restrict__ Wq) {
    int e = threadIdx.x;
    int c = blockIdx.x;
    float v;
    if (c < 128) {
        v = Wk[e * 128 + c];
    } else if (c < 256) {
        v = Wv[e * 128 + (c - 128)];
    } else if (c < 384) {
        int i = c - 256;
        float s = 0.f;
        for (int j = 0; j < 128; j++) s += Wp[e * 128 + j] * Wo[i * 128 + j];
        v = s;
    } else if (c < 512) {
        v = Wq[(128 + e) * 128 + (c - 384)];
    } else {
        v = Wq[(256 + e) * 128 + (c - 512)];
    }
    g_Wcat[e * PW + c] = v;
}

// ---------------- h_hat mean + qhat = h_hat @ Wq1 (+ vl/vf projections) ---------
__global__ void prep_kernel(const float* __restrict__ enc, const float* __restrict__ vl,
                            const float* __restrict__ vf, const float* __restrict__ Wq) {
    __shared__ float hh[EMB];
    int b = blockIdx.x, e = threadIdx.x;
    const float* p = enc + (size_t)b * SEQ * EMB + e;
    float s = 0.f;
    for (int i = 0; i < SEQ; i++) s += p[(size_t)i * EMB];
    hh[e] = s * (1.0f / (float)SEQ);
    __syncthreads();
    float q = 0.f;
    for (int k = 0; k < 128; k++) q += hh[k] * Wq[k * 128 + e];
    g_qhat[b * EMB + e] = q;
    if (b == 0) {
        float a = 0.f, c = 0.f;
        for (int k = 0; k < 128; k++) {
            a += vl[k] * Wq[(128 + k) * 128 + e];
            c += vf[k] * Wq[(256 + k) * 128 + e];
        }
        g_qvec[e] = a;
        g_qvec[128 + e] = c;
    }
}

// ---------------- SGEMM: g_P[204800,640] = enc[204800,128] @ g_Wcat[128,640] ----
__global__ __launch_bounds__(512, 1) void gemm_kernel(const float* __restrict__ A) {
    extern __shared__ float smg[];
    float* As = smg;               // As[k*132 + m]
    float* Bs = smg + 128 * 132;   // Bs[k*128 + n]
    int m0 = blockIdx.x * 128, n0 = blockIdx.y * 128;
    int tid = threadIdx.x;
#pragma unroll
    for (int it = 0; it < 32; it++) {
        int idx = tid + it * 512;
        int k = idx & 127, m = idx >> 7;
        As[k * 132 + m] = A[(size_t)(m0 + m) * 128 + k];
        Bs[m * 128 + k] = g_Wcat[m * PW + n0 + k];
    }
    __syncthreads();
    int tx = tid & 31, ty = tid >> 5;
    float acc[8][4];
#pragma unroll
    for (int i = 0; i < 8; i++)
#pragma unroll
        for (int j = 0; j < 4; j++) acc[i][j] = 0.f;
#pragma unroll 4
    for (int k = 0; k < 128; k++) {
        float4 a0 = *(float4*)&As[k * 132 + ty * 8];
        float4 a1 = *(float4*)&As[k * 132 + ty * 8 + 4];
        float4 b  = *(float4*)&Bs[k * 128 + tx * 4];
        float av[8] = {a0.x, a0.y, a0.z, a0.w, a1.x, a1.y, a1.z, a1.w};
#pragma unroll
        for (int i = 0; i < 8; i++) {
            acc[i][0] += av[i] * b.x;
            acc[i][1] += av[i] * b.y;
            acc[i][2] += av[i] * b.z;
            acc[i][3] += av[i] * b.w;
        }
    }
#pragma unroll
    for (int i = 0; i < 8; i++) {
        float* cr = &g_P[(size_t)(m0 + ty * 8 + i) * PW + n0 + tx * 4];
        *(float4*)cr = make_float4(acc[i][0], acc[i][1], acc[i][2], acc[i][3]);
    }
}

// -------- per-batch greedy decode: 1024 threads, K in regs, V+KP in SMEM --------
__global__ __launch_bounds__(1024, 1) void decode_kernel(float* __restrict__ outLogits,
                                                         float* __restrict__ outLogp,
                                                         float* __restrict__ outSol) {
    extern __shared__ float sm[];
    float*    Vsm  = sm;                        // 200*128 = 25600
    float*    KPsm = Vsm + SEQ * 128;           // 200*132 = 26400
    float*    attn = KPsm + SEQ * KPSTRIDE;     // 8*204
    float*    ctxp = attn + 8 * AST;            // 16*128
    float*    qv   = ctxp + 16 * 128;           // 128
    float*    ctx  = qv + EMB;                  // 128
    float*    wmax = ctx + EMB;                 // 32
    float*    wsum = wmax + 32;                 // 32
    float*    redv = wsum + 32;                 // 32
    float*    reds = redv + 32;                 // 32
    int*      redi = (int*)(reds + 32);         // 32
    unsigned* maskw = (unsigned*)(redi + 32);   // 8
    int*      sols  = (int*)(maskw + 8);        // 200
    float*    s_logp = (float*)(sols + SEQ);
    float*    s_bmax = s_logp + 1;
    int*      s_bi   = (int*)(s_bmax + 1);

    int tid = threadIdx.x, lane = tid & 31, w = tid >> 5;
    int b = blockIdx.x;
    const float* __restrict__ Pb = g_P + (size_t)b * SEQ * PW;

    // ---- one-time SMEM fills: V row-major [s][128], KP row-major [s][132] ----
    for (int i = tid; i < SEQ * EMB; i += 1024) {
        int s = i >> 7, e = i & 127;
        Vsm[s * 128 + e]      = Pb[(size_t)s * PW + 128 + e];
        KPsm[s * KPSTRIDE + e] = Pb[(size_t)s * PW + 256 + e];
    }

    // ---- K in registers: warp w = (head h = w>>2, quarter qt = w&3), 2 rows ----
    int h = w >> 2, qt = w & 3;
    float4 kreg[2][4];
#pragma unroll
    for (int r = 0; r < 2; r++) {
        int s = qt * 64 + (r << 5) + lane;
        if (s < SEQ) {
            const float4* kp = (const float4*)&Pb[(size_t)s * PW + (h << 4)];
            kreg[r][0] = kp[0]; kreg[r][1] = kp[1]; kreg[r][2] = kp[2]; kreg[r][3] = kp[3];
        } else {
            kreg[r][0] = kreg[r][1] = kreg[r][2] = kreg[r][3] = make_float4(0.f, 0.f, 0.f, 0.f);
        }
    }

    float qhat_r = 0.f, q2r = 0.f, q3r = 0.f;
    if (tid < 128) {
        qhat_r = g_qhat[b * EMB + tid];
        q2r = g_qvec[tid];          // t=0: last = vl
        q3r = g_qvec[128 + tid];    // t=0: first = vf
    }
    if (tid < 8) maskw[tid] = (tid == 0) ? 1u : 0u;
    if (tid == 0) { *s_logp = 0.f; sols[0] = 0; }
    __syncthreads();

    const float inv_scale = 0.08838834764831845f;   // 1/sqrt(128)

    for (int t = 0; t < TSTEPS; t++) {
        // ---- [1] accumulate previous CE + build q (pre-scaled by 1/sqrt(dh)) ----
        if (tid == 0 && t > 0) {
            float tot = 0.f;
#pragma unroll
            for (int i = 0; i < 25; i++) tot += reds[i];
            *s_logp += logf(tot);
        }
        if (tid < 128) qv[tid] = (qhat_r + q2r + q3r) * 0.25f;
        __syncthreads();

        // ---- [2a] scores from register K, per-warp max ----
        float sc[2];
        {
            const float4* qp = (const float4*)&qv[h << 4];
            float4 q0 = qp[0], q1 = qp[1], q2 = qp[2], q3 = qp[3];
#pragma unroll
            for (int r = 0; r < 2; r++) {
                int s = qt * 64 + (r << 5) + lane;
                float v;
                v  = q0.x * kreg[r][0].x + q0.y * kreg[r][0].y + q0.z * kreg[r][0].z + q0.w * kreg[r][0].w;
                v += q1.x * kreg[r][1].x + q1.y * kreg[r][1].y + q1.z * kreg[r][1].z + q1.w * kreg[r][1].w;
                v += q2.x * kreg[r][2].x + q2.y * kreg[r][2].y + q2.z * kreg[r][2].z + q2.w * kreg[r][2].w;
                v += q3.x * kreg[r][3].x + q3.y * kreg[r][3].y + q3.z * kreg[r][3].z + q3.w * kreg[r][3].w;
                bool ok = (s < SEQ) && !((maskw[2 * qt + r] >> lane) & 1u);
                sc[r] = ok ? v : NEGF;
            }
            float mx = fmaxf(sc[0], sc[1]);
#pragma unroll
            for (int o = 16; o; o >>= 1) mx = fmaxf(mx, __shfl_xor_sync(0xffffffffu, mx, o));
            if (lane == 0) wmax[w] = mx;
        }
        __syncthreads();

        // ---- [2b] exp against head max, store unnormalized attn, per-warp sum ----
        {
            float mx = fmaxf(fmaxf(wmax[4 * h], wmax[4 * h + 1]),
                             fmaxf(wmax[4 * h + 2], wmax[4 * h + 3]));
            float ssum = 0.f;
#pragma unroll
            for (int r = 0; r < 2; r++) {
                int s = qt * 64 + (r << 5) + lane;
                float er = expf(sc[r] - mx);      // NEGF -> 0
                ssum += er;
                if (s < SEQ) attn[h * AST + s] = er;
            }
#pragma unroll
            for (int o = 16; o; o >>= 1) ssum += __shfl_xor_sync(0xffffffffu, ssum, o);
            if (lane == 0) wsum[w] = ssum;
        }
        __syncthreads();

        // ---- [3] ctx partials: warps 0-15, 13 s each, V float4 from SMEM ----
        if (w < 16) {
            int s0 = w * 13;
            int hd = lane >> 2;
            const float* arow = &attn[hd * AST];
            float a0 = 0.f, a1 = 0.f, a2 = 0.f, a3 = 0.f;
#pragma unroll
            for (int i = 0; i < 13; i++) {
                int s = s0 + i;
                if (s < SEQ) {
                    float a = arow[s];
                    float4 vv = *(const float4*)&Vsm[s * 128 + (lane << 2)];
                    a0 += a * vv.x; a1 += a * vv.y; a2 += a * vv.z; a3 += a * vv.w;
                }
            }
            *(float4*)&ctxp[w * 128 + (lane << 2)] = make_float4(a0, a1, a2, a3);
        }
        __syncthreads();

        // ---- [4] ctx combine + softmax normalization ----
        if (tid < 128) {
            float s = 0.f;
#pragma unroll
            for (int i = 0; i < 16; i++) s += ctxp[i * 128 + tid];
            int hd = tid >> 4;
            float inv = 1.f / (wsum[4 * hd] + wsum[4 * hd + 1] + wsum[4 * hd + 2] + wsum[4 * hd + 3]);
            ctx[tid] = s * inv;
        }
        __syncthreads();

        // ---- [5] pointer logits: warps 0-24, 8 s per warp, 4 e-quarters/lane ----
        float myval = NEGF;
        if (w < 25) {
            int sl = lane & 7, qq = lane >> 3;
            int s = (w << 3) + sl;
            const float* kp = &KPsm[s * KPSTRIDE + (qq << 5)];
            const float* cx = &ctx[qq << 5];
            float z0 = 0.f, z1 = 0.f, z2 = 0.f, z3 = 0.f;
#pragma unroll
            for (int j = 0; j < 8; j++) {
                float4 c4 = *(const float4*)&cx[j << 2];
                float4 k4 = *(const float4*)&kp[j << 2];
                z0 += c4.x * k4.x; z1 += c4.y * k4.y;
                z2 += c4.z * k4.z; z3 += c4.w * k4.w;
            }
            float z = (z0 + z1) + (z2 + z3);
            z += __shfl_xor_sync(0xffffffffu, z, 8);
            z += __shfl_xor_sync(0xffffffffu, z, 16);
            float u = 10.f * tanhf(z * inv_scale);
            bool masked = (maskw[s >> 5] >> (s & 31)) & 1u;
            if (qq == 0) {
                outLogits[((size_t)b * TSTEPS + t) * SEQ + s] = u;
                if (!masked) myval = u;   // CE term: one lane per s
            }
            // argmax: all 4 quarter-lanes hold the same (val, s) — duplicates are harmless
            float aval = masked ? NEGF : u;
            int vidx = s;
#pragma unroll
            for (int o = 16; o; o >>= 1) {
                float ov = __shfl_xor_sync(0xffffffffu, aval, o);
                int   oi = __shfl_xor_sync(0xffffffffu, vidx, o);
                if (ov > aval || (ov == aval && oi < vidx)) { aval = ov; vidx = oi; }
            }
            if (lane == 0) { redv[w] = aval; redi[w] = vidx; }
        }
        __syncthreads();

        // ---- [6] argmax finalize + mask/sol update ----
        if (tid == 0) {
            float bm = redv[0]; int bi = redi[0];
#pragma unroll
            for (int i = 1; i < 25; i++)
                if (redv[i] > bm) { bm = redv[i]; bi = redi[i]; }
            *s_bmax = bm; *s_bi = bi;
            maskw[bi >> 5] |= (1u << (bi & 31));
            sols[t + 1] = bi;
        }
        __syncthreads();

        // ---- [7] CE exp-sums + prefetch next-step q rows ----
        if (w < 25) {
            float e = expf(myval - *s_bmax);   // masked / non-owner lanes -> 0
#pragma unroll
            for (int o = 16; o; o >>= 1) e += __shfl_xor_sync(0xffffffffu, e, o);
            if (lane == 0) reds[w] = e;
        }
        if (tid < 128) {
            int bi = *s_bi;
            q2r = Pb[(size_t)bi * PW + 384 + tid];             // Q2[b, idx]
            if (t == 0) q3r = Pb[(size_t)bi * PW + 512 + tid]; // Q3[b, idx0]
        }
        __syncthreads();
    }

    if (tid == 0 && outLogp) {
        float tot = 0.f;
        for (int i = 0; i < 25; i++) tot += reds[i];
        outLogp[b] = *s_logp + logf(tot);
    }
    if (outSol && tid < SEQ) outSol[b * SEQ + tid] = (float)sols[tid];
}

// -------------------------------- launcher --------------------------------------
extern "C" void kernel_launch(void* const* d_in, const int* in_sizes, int n_in,
                              void* d_out, int out_size) {
    const float* enc = (const float*)d_in[0];
    const float* vl = (const float*)d_in[3];
    const float* vf = (const float*)d_in[4];
    const float* Wq = (const float*)d_in[5];
    const float* Wk = (const float*)d_in[6];
    const float* Wv = (const float*)d_in[7];
    const float* Wo = (const float*)d_in[8];
    const float* Wp = (const float*)d_in[9];

    float* out = (float*)d_out;
    size_t L = (size_t)BATCH * TSTEPS * SEQ;
    float* outLogp = nullptr;
    float* outSol  = nullptr;
    if ((size_t)out_size >= L + BATCH) outLogp = out + L;
    if ((size_t)out_size >= L + BATCH + (size_t)BATCH * SEQ) outSol = out + L + BATCH;

    const int gemm_smem = (128 * 132 + 128 * 128) * 4;   // 133,120 B
    // V 25600 + KP 26400 + attn 1632 + ctxp 2048 + qv 128 + ctx 128
    // + wmax/wsum/redv/reds/redi 160 + maskw 8 + sols 200 + 4
    const int decode_smem = (25600 + 26400 + 1632 + 2048 + 128 + 128 + 160 + 8 + 200 + 4) * 4;
    cudaFuncSetAttribute(gemm_kernel,   cudaFuncAttributeMaxDynamicSharedMemorySize, gemm_smem);
    cudaFuncSetAttribute(decode_kernel, cudaFuncAttributeMaxDynamicSharedMemorySize, decode_smem);

    wcat_kernel<<<PW, 128>>>(Wk, Wv, Wo, Wp, Wq);
    prep_kernel<<<BATCH, 128>>>(enc, vl, vf, Wq);
    gemm_kernel<<<dim3(BATCH * SEQ / 128, PW / 128), 512, gemm_smem>>>(enc);
    decode_kernel<<<BATCH, 1024, decode_smem>>>(out, outLogp, outSol);
}

// round 7
// speedup vs baseline: 2.5156x; 1.1799x over previous
#include <cuda_runtime.h>
#include <math.h>

#define BATCH 1024
#define SEQ   200
#define EMB   128
#define TSTEPS 199
#define PW    640      // P columns: [K(128) | V(128) | KP(128) | Q2(128) | Q3(128)]
#define AST   204      // attn smem row stride (per head)
#define KPST  132      // KP smem row stride (per s)
#define NEGF  (-3.402823466e38f)

// ---------------- device scratch ----------------
__device__ float g_P[(size_t)BATCH * SEQ * PW];
__device__ float g_Wcat[EMB * PW];
__device__ float g_qhat[BATCH * EMB];
__device__ float g_qvec[2 * EMB];

// ---------------- build combined weights: [Wk | Wv | Wp@Wo^T | Wq2 | Wq3] -------
__global__ void wcat_kernel(const float* __restrict__ Wk, const float* __restrict__ Wv,
                            const float* __restrict__ Wo, const float* __restrict__ Wp,
                            const float* __restrict__ Wq) {
    int e = threadIdx.x;
    int c = blockIdx.x;
    float v;
    if (c < 128) {
        v = Wk[e * 128 + c];
    } else if (c < 256) {
        v = Wv[e * 128 + (c - 128)];
    } else if (c < 384) {
        int i = c - 256;
        float s = 0.f;
        for (int j = 0; j < 128; j++) s += Wp[e * 128 + j] * Wo[i * 128 + j];
        v = s;
    } else if (c < 512) {
        v = Wq[(128 + e) * 128 + (c - 384)];
    } else {
        v = Wq[(256 + e) * 128 + (c - 512)];
    }
    g_Wcat[e * PW + c] = v;
}

// ---------------- h_hat mean + qhat = h_hat @ Wq1 (+ vl/vf projections) ---------
__global__ void prep_kernel(const float* __restrict__ enc, const float* __restrict__ vl,
                            const float* __restrict__ vf, const float* __restrict__ Wq) {
    __shared__ float hh[EMB];
    int b = blockIdx.x, e = threadIdx.x;
    const float* p = enc + (size_t)b * SEQ * EMB + e;
    float s = 0.f;
    for (int i = 0; i < SEQ; i++) s += p[(size_t)i * EMB];
    hh[e] = s * (1.0f / (float)SEQ);
    __syncthreads();
    float q = 0.f;
    for (int k = 0; k < 128; k++) q += hh[k] * Wq[k * 128 + e];
    g_qhat[b * EMB + e] = q;
    if (b == 0) {
        float a = 0.f, c = 0.f;
        for (int k = 0; k < 128; k++) {
            a += vl[k] * Wq[(128 + k) * 128 + e];
            c += vf[k] * Wq[(256 + k) * 128 + e];
        }
        g_qvec[e] = a;
        g_qvec[128 + e] = c;
    }
}

// ---------------- SGEMM: g_P[204800,640] = enc[204800,128] @ g_Wcat[128,640] ----
__global__ __launch_bounds__(512, 1) void gemm_kernel(const float* __restrict__ A) {
    extern __shared__ float smg[];
    float* As = smg;               // As[k*132 + m]
    float* Bs = smg + 128 * 132;   // Bs[k*128 + n]
    int m0 = blockIdx.x * 128, n0 = blockIdx.y * 128;
    int tid = threadIdx.x;
#pragma unroll
    for (int it = 0; it < 32; it++) {
        int idx = tid + it * 512;
        int k = idx & 127, m = idx >> 7;
        As[k * 132 + m] = A[(size_t)(m0 + m) * 128 + k];
        Bs[m * 128 + k] = g_Wcat[m * PW + n0 + k];
    }
    __syncthreads();
    int tx = tid & 31, ty = tid >> 5;
    float acc[8][4];
#pragma unroll
    for (int i = 0; i < 8; i++)
#pragma unroll
        for (int j = 0; j < 4; j++) acc[i][j] = 0.f;
#pragma unroll 4
    for (int k = 0; k < 128; k++) {
        float4 a0 = *(float4*)&As[k * 132 + ty * 8];
        float4 a1 = *(float4*)&As[k * 132 + ty * 8 + 4];
        float4 b  = *(float4*)&Bs[k * 128 + tx * 4];
        float av[8] = {a0.x, a0.y, a0.z, a0.w, a1.x, a1.y, a1.z, a1.w};
#pragma unroll
        for (int i = 0; i < 8; i++) {
            acc[i][0] += av[i] * b.x;
            acc[i][1] += av[i] * b.y;
            acc[i][2] += av[i] * b.z;
            acc[i][3] += av[i] * b.w;
        }
    }
#pragma unroll
    for (int i = 0; i < 8; i++) {
        float* cr = &g_P[(size_t)(m0 + ty * 8 + i) * PW + n0 + tx * 4];
        *(float4*)cr = make_float4(acc[i][0], acc[i][1], acc[i][2], acc[i][3]);
    }
}

// ------ decode: 512 thr, K in regs, V+KP in SMEM, 5 barriers/step, no max-pass ------
__global__ __launch_bounds__(512) void decode_kernel(float* __restrict__ outLogits,
                                                     float* __restrict__ outLogp,
                                                     float* __restrict__ outSol) {
    extern __shared__ float sm[];
    float*    Vsm  = sm;                        // 200*128 = 25600
    float*    KPsm = Vsm + SEQ * 128;           // 200*132 = 26400
    float*    attn = KPsm + SEQ * KPST;         // 8*204 (unnormalized)
    float*    ctxp = attn + 8 * AST;            // 16*128
    float*    qv   = ctxp + 16 * 128;           // 128
    float*    ctx  = qv + EMB;                  // 128
    float*    wsum = ctx + EMB;                 // 16
    float*    redv = wsum + 16;                 // 16
    int*      redi = (int*)(redv + 16);         // 16
    float*    reds = (float*)(redi + 16);       // 2*16 double-buffered CE sums
    unsigned* maskw = (unsigned*)(reds + 32);   // 8
    int*      sols  = (int*)(maskw + 8);        // 200
    float*    s_logp = (float*)(sols + SEQ);    // 1

    int tid = threadIdx.x, lane = tid & 31, w = tid >> 5;
    int b = blockIdx.x;
    const float* __restrict__ Pb = g_P + (size_t)b * SEQ * PW;

    // ---- one-time SMEM fills: V row-major [s][128], KP row-major [s][132] ----
    for (int i = tid; i < SEQ * EMB; i += 512) {
        int s = i >> 7, e = i & 127;
        Vsm[s * 128 + e]   = Pb[(size_t)s * PW + 128 + e];
        KPsm[s * KPST + e] = Pb[(size_t)s * PW + 256 + e];
    }

    // ---- K in registers: warp w = (head h = w>>1, sub = w&1), 4 rows of s ----
    int h = w >> 1, sub = w & 1;
    float4 kreg[4][4];
#pragma unroll
    for (int r = 0; r < 4; r++) {
        int s = sub * 128 + (r << 5) + lane;
        if (s < SEQ) {
            const float4* kp = (const float4*)&Pb[(size_t)s * PW + (h << 4)];
            kreg[r][0] = kp[0]; kreg[r][1] = kp[1]; kreg[r][2] = kp[2]; kreg[r][3] = kp[3];
        } else {
            kreg[r][0] = kreg[r][1] = kreg[r][2] = kreg[r][3] = make_float4(0.f, 0.f, 0.f, 0.f);
        }
    }

    float qhat_r = 0.f, q2r = 0.f, q3r = 0.f;
    if (tid < 128) {
        qhat_r = g_qhat[b * EMB + tid];
        q2r = g_qvec[tid];          // t=0: last = vl
        q3r = g_qvec[128 + tid];    // t=0: first = vf
        qv[tid] = (qhat_r + q2r + q3r) * 0.25f;   // initial q, pre-scaled 1/sqrt(dh)
    }
    if (tid < 8) maskw[tid] = (tid == 0) ? 1u : 0u;
    if (tid == 0) { *s_logp = 0.f; sols[0] = 0; }
    __syncthreads();

    const float inv_scale = 0.08838834764831845f;   // 1/sqrt(128)

    for (int t = 0; t < TSTEPS; t++) {
        // ---- [B] scores (register K) + exp (no max pass) + attn store + warp sum ----
        {
            const float4* qp = (const float4*)&qv[h << 4];
            float4 q0 = qp[0], q1 = qp[1], q2 = qp[2], q3 = qp[3];
            float ssum = 0.f;
#pragma unroll
            for (int r = 0; r < 4; r++) {
                int s = sub * 128 + (r << 5) + lane;
                float v;
                v  = q0.x * kreg[r][0].x + q0.y * kreg[r][0].y + q0.z * kreg[r][0].z + q0.w * kreg[r][0].w;
                v += q1.x * kreg[r][1].x + q1.y * kreg[r][1].y + q1.z * kreg[r][1].z + q1.w * kreg[r][1].w;
                v += q2.x * kreg[r][2].x + q2.y * kreg[r][2].y + q2.z * kreg[r][2].z + q2.w * kreg[r][2].w;
                v += q3.x * kreg[r][3].x + q3.y * kreg[r][3].y + q3.z * kreg[r][3].z + q3.w * kreg[r][3].w;
                bool ok = (s < SEQ) && !((maskw[4 * sub + r] >> lane) & 1u);
                float er = expf(ok ? v : NEGF);   // masked/invalid -> 0
                ssum += er;
                if (s < SEQ) attn[h * AST + s] = er;
            }
#pragma unroll
            for (int o = 16; o; o >>= 1) ssum += __shfl_xor_sync(0xffffffffu, ssum, o);
            if (lane == 0) wsum[w] = ssum;
        }
        __syncthreads();

        // ---- [C] ctx partials: 16 warps x 13 s, V float4 from SMEM ----
        {
            int s0 = w * 13;                      // covers 0..207
            int hd = lane >> 2;
            const float* arow = &attn[hd * AST];
            float a0 = 0.f, a1 = 0.f, a2 = 0.f, a3 = 0.f;
#pragma unroll
            for (int i = 0; i < 13; i++) {
                int s = s0 + i;
                if (s < SEQ) {
                    float a = arow[s];
                    float4 vv = *(const float4*)&Vsm[s * 128 + (lane << 2)];
                    a0 += a * vv.x; a1 += a * vv.y; a2 += a * vv.z; a3 += a * vv.w;
                }
            }
            *(float4*)&ctxp[w * 128 + (lane << 2)] = make_float4(a0, a1, a2, a3);
        }
        __syncthreads();

        // ---- [D] ctx combine + softmax normalization ----
        if (tid < 128) {
            float s = 0.f;
#pragma unroll
            for (int i = 0; i < 16; i++) s += ctxp[i * 128 + tid];
            int hd = tid >> 4;
            ctx[tid] = s * (1.f / (wsum[2 * hd] + wsum[2 * hd + 1]));
        }
        __syncthreads();

        // ---- [E] pointer logits: 13 warps, 2 threads/s, float4 KP + ctx ----
        float myval = NEGF;
        if (w < 13) {
            int sl = lane & 15, half = lane >> 4;
            int s = (w << 4) + sl;                // < 208; s>=200 lanes produce garbage, gated below
            int sv = (s < SEQ) ? s : (SEQ - 1);
            const float* kp = &KPsm[sv * KPST + (half << 6)];
            const float* cx = &ctx[half << 6];
            float z0 = 0.f, z1 = 0.f, z2 = 0.f, z3 = 0.f;
#pragma unroll
            for (int j = 0; j < 16; j++) {
                float4 c4 = *(const float4*)&cx[j << 2];
                float4 k4 = *(const float4*)&kp[j << 2];
                z0 += c4.x * k4.x; z1 += c4.y * k4.y;
                z2 += c4.z * k4.z; z3 += c4.w * k4.w;
            }
            float z = (z0 + z1) + (z2 + z3);
            z += __shfl_xor_sync(0xffffffffu, z, 16);
            float u = 10.f * tanhf(z * inv_scale);
            bool valid = (s < SEQ);
            bool masked = valid ? ((maskw[s >> 5] >> (s & 31)) & 1u) : true;
            if (valid && half == 0) {
                outLogits[((size_t)b * TSTEPS + t) * SEQ + s] = u;
                if (!masked) myval = u;           // CE owner: one lane per s
            }
            float aval = masked ? NEGF : u;       // duplicated on both halves: harmless
            int vidx = valid ? s : 0x7fffffff;
#pragma unroll
            for (int o = 16; o; o >>= 1) {
                float ov = __shfl_xor_sync(0xffffffffu, aval, o);
                int   oi = __shfl_xor_sync(0xffffffffu, vidx, o);
                if (ov > aval || (ov == aval && oi < vidx)) { aval = ov; vidx = oi; }
            }
            if (lane == 0) { redv[w] = aval; redi[w] = vidx; }
        }
        __syncthreads();

        // ---- [F] all-thread candidate scan + CE + mask + q prefetch + qv build ----
        {
            // previous step's CE sum (other buffer) -> logp, race-free via parity
            if (tid == 0 && t > 0) {
                const float* rp = &reds[((t - 1) & 1) * 16];
                float tot = 0.f;
#pragma unroll
                for (int i = 0; i < 13; i++) tot += rp[i];
                *s_logp += logf(tot);
            }
            float bm = redv[0]; int bi = redi[0];
#pragma unroll
            for (int i = 1; i < 13; i++) {
                float v = redv[i];
                if (v > bm) { bm = v; bi = redi[i]; }
            }
            // issue q loads early (L2) — consumed at end of this phase
            if (tid < 128) {
                q2r = Pb[(size_t)bi * PW + 384 + tid];             // Q2[b, idx]
                if (t == 0) q3r = Pb[(size_t)bi * PW + 512 + tid]; // Q3[b, idx0]
            }
            if (w < 13) {
                float e = expf(myval - bm);   // masked/non-owner -> 0
#pragma unroll
                for (int o = 16; o; o >>= 1) e += __shfl_xor_sync(0xffffffffu, e, o);
                if (lane == 0) reds[(t & 1) * 16 + w] = e;
            }
            if (tid == 0) {
                maskw[bi >> 5] |= (1u << (bi & 31));
                sols[t + 1] = bi;
            }
            if (tid < 128) qv[tid] = (qhat_r + q2r + q3r) * 0.25f;
        }
        __syncthreads();
    }

    if (tid == 0 && outLogp) {
        const float* rp = &reds[((TSTEPS - 1) & 1) * 16];
        float tot = 0.f;
        for (int i = 0; i < 13; i++) tot += rp[i];
        outLogp[b] = *s_logp + logf(tot);
    }
    if (outSol && tid < SEQ) outSol[b * SEQ + tid] = (float)sols[tid];
}

// -------------------------------- launcher --------------------------------------
extern "C" void kernel_launch(void* const* d_in, const int* in_sizes, int n_in,
                              void* d_out, int out_size) {
    const float* enc = (const float*)d_in[0];
    const float* vl = (const float*)d_in[3];
    const float* vf = (const float*)d_in[4];
    const float* Wq = (const float*)d_in[5];
    const float* Wk = (const float*)d_in[6];
    const float* Wv = (const float*)d_in[7];
    const float* Wo = (const float*)d_in[8];
    const float* Wp = (const float*)d_in[9];

    float* out = (float*)d_out;
    size_t L = (size_t)BATCH * TSTEPS * SEQ;
    float* outLogp = nullptr;
    float* outSol  = nullptr;
    if ((size_t)out_size >= L + BATCH) outLogp = out + L;
    if ((size_t)out_size >= L + BATCH + (size_t)BATCH * SEQ) outSol = out + L + BATCH;

    const int gemm_smem = (128 * 132 + 128 * 128) * 4;   // 133,120 B
    // V 25600 + KP 26400 + attn 1632 + ctxp 2048 + qv 128 + ctx 128
    // + wsum/redv/redi 48 + reds 32 + maskw 8 + sols 200 + logp 1  = 56,225 floats
    const int decode_smem = 56232 * 4;                   // 224,928 B
    cudaFuncSetAttribute(gemm_kernel,   cudaFuncAttributeMaxDynamicSharedMemorySize, gemm_smem);
    cudaFuncSetAttribute(decode_kernel, cudaFuncAttributeMaxDynamicSharedMemorySize, decode_smem);

    wcat_kernel<<<PW, 128>>>(Wk, Wv, Wo, Wp, Wq);
    prep_kernel<<<BATCH, 128>>>(enc, vl, vf, Wq);
    gemm_kernel<<<dim3(BATCH * SEQ / 128, PW / 128), 512, gemm_smem>>>(enc);
    decode_kernel<<<BATCH, 512, decode_smem>>>(out, outLogp, outSol);
}